// round 12
// baseline (speedup 1.0000x reference)
#include <cuda_runtime.h>
#include <cuda_fp16.h>
#include <cstdint>

typedef unsigned long long ull;

#define H 256
#define S 200
#define BSZ 1024
#define BT 8
#define NITEMS 50000
#define KCP 32          // cached kp-pairs of W1/W2 (fp16) in smem
#define ODE_ST 12       // streamed ODE ring iters per half (4 kp each) = 48 kp
#define GRU_IT 32       // GRU ring iters per half (2 kp each) = 64 kp

// ---------------- device globals ----------------
__device__ ull     g_WhhS[2 * GRU_IT * 256 * 6];   // fp32 pairs, ring-layout (48B per (half,it,j))
__device__ __half2 g_W1H[128 * 256];               // kp-major fp16 pairs (cached source)
__device__ __half2 g_W2H[128 * 256];
__device__ __half2 g_W1S[2 * ODE_ST * 256 * 4];    // streamed ring layout (16B per (half,it,j))
__device__ __half2 g_W2S[2 * ODE_ST * 256 * 4];
__device__ float   g_Etab[(size_t)NITEMS * 768];
__device__ float   g_hfin[BSZ * H];

// ---------------- helpers ----------------
__device__ __forceinline__ void ffma2(ull& d, ull a, ull b) {
    asm("fma.rn.f32x2 %0, %1, %2, %3;" : "=l"(d) : "l"(a), "l"(b), "l"(d));
}
__device__ __forceinline__ ull pack2(float lo, float hi) {
    ull r; asm("mov.b64 %0, {%1, %2};" : "=l"(r) : "f"(lo), "f"(hi)); return r;
}
__device__ __forceinline__ void unpack2(ull v, float& lo, float& hi) {
    asm("mov.b64 {%0, %1}, %2;" : "=f"(lo), "=f"(hi) : "l"(v));
}
__device__ __forceinline__ float hsum2(ull v) {
    float lo, hi; unpack2(v, lo, hi); return lo + hi;
}
__device__ __forceinline__ ull h2ull(__half2 h) {
    float2 f = __half22float2(h);
    return pack2(f.x, f.y);
}
__device__ __forceinline__ float sigm(float v) { return 1.0f / (1.0f + __expf(-v)); }
__device__ __forceinline__ float ftanh(float v) {
    float e = __expf(2.0f * v);
    return 1.0f - 2.0f / (e + 1.0f);
}
__device__ __forceinline__ void cp16(uint32_t dst, const void* src) {
    asm volatile("cp.async.cg.shared.global [%0], [%1], 16;" :: "r"(dst), "l"(src) : "memory");
}
__device__ __forceinline__ void cp_commit() { asm volatile("cp.async.commit_group;" ::: "memory"); }

// ---------------- weight packing ----------------
__global__ void prep_pack(const float* __restrict__ W_hh,
                          const float* __restrict__ W1,
                          const float* __restrict__ W2)
{
    int i = blockIdx.x * blockDim.x + threadIdx.x;
    if (i < 2 * GRU_IT * 256 * 6) {                 // 98304
        int u = i % 6;
        int j = (i / 6) & 255;
        int it = (i / 1536) & 31;
        int half = i / 49152;
        int kp = half * 64 + 2 * it + (u >= 3 ? 1 : 0);
        int g = u % 3;                               // gate r,z,n
        const float* row = W_hh + (size_t)(g * 256 + j) * 256;
        g_WhhS[i] = pack2(row[2 * kp], row[2 * kp + 1]);
    }
    if (i < 128 * 256) {
        int kp = i >> 8, jo = i & 255;
        g_W1H[i] = __floats2half2_rn(W1[jo * 256 + 2 * kp], W1[jo * 256 + 2 * kp + 1]);
        g_W2H[i] = __floats2half2_rn(W2[jo * 256 + 2 * kp], W2[jo * 256 + 2 * kp + 1]);
    }
    if (i < 2 * ODE_ST * 256 * 4) {                 // 24576
        int u = i & 3;
        int j = (i >> 2) & 255;
        int it = (i >> 10) % ODE_ST;
        int half = i / (ODE_ST * 1024);
        int kp = KCP + half * 48 + it * 4 + u;
        g_W1S[i] = __floats2half2_rn(W1[j * 256 + 2 * kp], W1[j * 256 + 2 * kp + 1]);
        g_W2S[i] = __floats2half2_rn(W2[j * 256 + 2 * kp], W2[j * 256 + 2 * kp + 1]);
    }
}

// ---------------- generic C[M,N] = A[M,256] @ B[N,256]^T + bias ----------------
#define GM 64
#define GN 128

__global__ void __launch_bounds__(256) gemm_nt(
    const float* __restrict__ A, const float* __restrict__ B,
    const float* __restrict__ bias, float* __restrict__ C,
    int M, int N)
{
    __shared__ float shA[GM][H];
    __shared__ float shW[8][132];

    const int n0 = blockIdx.x * GN;
    const int m0 = blockIdx.y * GM;
    const int tid = threadIdx.x;

#pragma unroll
    for (int i = 0; i < 16; i++) {
        int idx = tid + i * 256;
        int r = idx >> 6, c4 = idx & 63;
        int m = m0 + r;
        float4 v = make_float4(0.f, 0.f, 0.f, 0.f);
        if (m < M) v = *(const float4*)&A[(size_t)m * H + c4 * 4];
        *(float4*)&shA[r][c4 * 4] = v;
    }

    const int tn = tid & 31;
    const int tb = tid >> 5;
    const int nl0 = tn * 4;

    ull acc[8][2];
#pragma unroll
    for (int bb = 0; bb < 8; bb++) { acc[bb][0] = 0ull; acc[bb][1] = 0ull; }

    __syncthreads();

    for (int k0 = 0; k0 < H; k0 += 8) {
#pragma unroll
        for (int i = 0; i < 4; i++) {
            int idx = tid + i * 256;
            int nl = idx >> 3, kc = idx & 7;
            int n = n0 + nl;
            shW[kc][nl] = (n < N) ? B[(size_t)n * H + k0 + kc] : 0.f;
        }
        __syncthreads();
#pragma unroll
        for (int kc = 0; kc < 8; kc++) {
            ulonglong2 wv = *(const ulonglong2*)&shW[kc][nl0];
#pragma unroll
            for (int bb = 0; bb < 8; bb++) {
                float hb = shA[tb * 8 + bb][k0 + kc];
                ull hp = pack2(hb, hb);
                ffma2(acc[bb][0], hp, wv.x);
                ffma2(acc[bb][1], hp, wv.y);
            }
        }
        __syncthreads();
    }

    const int nbase = n0 + nl0;
#pragma unroll
    for (int bb = 0; bb < 8; bb++) {
        int m = m0 + tb * 8 + bb;
        if (m >= M) continue;
        float o0, o1, o2, o3;
        unpack2(acc[bb][0], o0, o1);
        unpack2(acc[bb][1], o2, o3);
        if (nbase + 3 < N) {
            float4 o;
            o.x = o0 + bias[nbase + 0];
            o.y = o1 + bias[nbase + 1];
            o.z = o2 + bias[nbase + 2];
            o.w = o3 + bias[nbase + 3];
            *(float4*)&C[(size_t)m * N + nbase] = o;
        } else {
            float ov[4] = {o0, o1, o2, o3};
#pragma unroll
            for (int nn = 0; nn < 4; nn++) {
                int n = nbase + nn;
                if (n < N) C[(size_t)m * N + n] = ov[nn] + bias[n];
            }
        }
    }
}

// ---------------- ODE partial matmul: cached fp16 + ring-streamed fp16 ----------------
__device__ __forceinline__ void mm_partial(const float (*__restrict__ src)[H],
                                           const __half2* __restrict__ ws,
                                           const __half2* __restrict__ gS,
                                           ull* __restrict__ ring, uint32_t ring_s,
                                           int j, int half, int tid, ull* acc)
{
    const char* gbase = (const char*)gS + (((size_t)half * ODE_ST) * 256 + j) * 16;

    // prologue: fill 4 ring stages (thread-private 16B slots)
#pragma unroll
    for (int d = 0; d < 4; d++) {
        cp16(ring_s + (uint32_t)(d * 512 + tid) * 16, gbase + (size_t)d * 256 * 16);
        cp_commit();
    }

#pragma unroll
    for (int r = 0; r < BT; r++) acc[r] = 0ull;

    // cached 16 kp for this half (hidden behind ring prologue latency)
    const int kc0 = half * 16;
#pragma unroll 2
    for (int c = 0; c < 8; c++) {
        int kp = kc0 + 2 * c;
        ull w0 = h2ull(ws[kp * 256 + j]);
        ull w1 = h2ull(ws[kp * 256 + 256 + j]);
#pragma unroll
        for (int r = 0; r < BT; r++) {
            ulonglong2 sv = *(const ulonglong2*)&src[r][2 * kp];
            ffma2(acc[r], sv.x, w0);
            ffma2(acc[r], sv.y, w1);
        }
    }

    const int kb0 = KCP + half * 48;
    // main streamed loop (refill keeps depth 4)
#pragma unroll 1
    for (int i = 0; i < 8; i++) {
        asm volatile("cp.async.wait_group 3;" ::: "memory");
        ulonglong2 wv = *(const ulonglong2*)&ring[(size_t)((i & 3) * 512 + tid) * 2];
        cp16(ring_s + (uint32_t)((i & 3) * 512 + tid) * 16, gbase + (size_t)(i + 4) * 256 * 16);
        cp_commit();
        uint32_t u0 = (uint32_t)wv.x, u1 = (uint32_t)(wv.x >> 32);
        uint32_t u2 = (uint32_t)wv.y, u3 = (uint32_t)(wv.y >> 32);
        ull w0 = h2ull(*(__half2*)&u0), w1 = h2ull(*(__half2*)&u1);
        ull w2 = h2ull(*(__half2*)&u2), w3 = h2ull(*(__half2*)&u3);
        const int kp = kb0 + 4 * i;
#pragma unroll
        for (int r = 0; r < BT; r++) {
            ulonglong2 sa = *(const ulonglong2*)&src[r][2 * kp];
            ulonglong2 sb = *(const ulonglong2*)&src[r][2 * kp + 4];
            ffma2(acc[r], sa.x, w0);
            ffma2(acc[r], sa.y, w1);
            ffma2(acc[r], sb.x, w2);
            ffma2(acc[r], sb.y, w3);
        }
    }
    asm volatile("cp.async.wait_group 0;" ::: "memory");
#pragma unroll 1
    for (int i = 8; i < 12; i++) {
        ulonglong2 wv = *(const ulonglong2*)&ring[(size_t)((i & 3) * 512 + tid) * 2];
        uint32_t u0 = (uint32_t)wv.x, u1 = (uint32_t)(wv.x >> 32);
        uint32_t u2 = (uint32_t)wv.y, u3 = (uint32_t)(wv.y >> 32);
        ull w0 = h2ull(*(__half2*)&u0), w1 = h2ull(*(__half2*)&u1);
        ull w2 = h2ull(*(__half2*)&u2), w3 = h2ull(*(__half2*)&u3);
        const int kp = kb0 + 4 * i;
#pragma unroll
        for (int r = 0; r < BT; r++) {
            ulonglong2 sa = *(const ulonglong2*)&src[r][2 * kp];
            ulonglong2 sb = *(const ulonglong2*)&src[r][2 * kp + 4];
            ffma2(acc[r], sa.x, w0);
            ffma2(acc[r], sa.y, w1);
            ffma2(acc[r], sb.x, w2);
            ffma2(acc[r], sb.y, w3);
        }
    }
}

// ---------------- recurrent kernel: 512 threads, K-split, per-thread cp.async rings ----------------
__global__ void __launch_bounds__(512) rec_kernel(
    const int* __restrict__ x, const float* __restrict__ tt,
    const float* __restrict__ b_hh,
    const float* __restrict__ b1, const float* __restrict__ b2)
{
    extern __shared__ ull dynsmem[];
    __half2* sW1 = (__half2*)dynsmem;                    // 32 KB
    __half2* sW2 = sW1 + KCP * 256;                      // 32 KB
    ull* ring = (ull*)(sW2 + KCP * 256);                 // 98304 B (GRU 48B-slots / ODE 16B-slots, phase-exclusive)
    float* fbase = (float*)(ring + 12288);
    float (*sh_h)[H] = (float (*)[H])fbase;
    float (*sh_a)[H] = (float (*)[H])(fbase + BT * H);
    float (*sh_t)[H] = (float (*)[H])(fbase + 2 * BT * H);
    float* red = fbase + 3 * BT * H;                     // 2 halves x 3 planes x 4 rows x 256 = 24 KB
    int*   sh_it = (int*)(red + 2 * 3 * 4 * H);
    float* sh_dt = (float*)(sh_it + BT);

    const int tid = threadIdx.x;
    const int j = tid & 255;
    const int half = tid >> 8;
    const int r0 = half * 4;
    const int b0 = blockIdx.x * BT;
    const uint32_t ring_s = (uint32_t)__cvta_generic_to_shared(ring);

#define RG(hh, g, q) ((((hh) * 3 + (g)) * 4 + (q)) * H + j)

    for (int i = tid; i < KCP * 256; i += 512) { sW1[i] = g_W1H[i]; sW2[i] = g_W2H[i]; }

    const float bhhr = b_hh[j], bhhz = b_hh[H + j], bhhn = b_hh[2 * H + j];
    const float b1j = b1[j], b2j = b2[j];

#pragma unroll
    for (int q = 0; q < 4; q++) sh_h[r0 + q][j] = 0.f;
    float hnew[4];
#pragma unroll
    for (int q = 0; q < 4; q++) hnew[q] = 0.f;
    __syncthreads();

    const char* gwb = (const char*)g_WhhS + (((size_t)half * GRU_IT) * 256 + j) * 48;

    for (int s = 0; s < S; s++) {
        if (tid < BT) {
            sh_it[tid] = x[(b0 + tid) * S + s];
            float tc = tt[(b0 + tid) * S + s];
            float d = 0.f;
            if (s < S - 1) {
                float tn = tt[(b0 + tid) * S + s + 1];
                d = fmaxf(tn, tc + 1e-5f) - tc;
            }
            sh_dt[tid] = d;
        }
        __syncthreads();   // (A)

        // GRU ring prologue: 4 stages x 48B, thread-private
#pragma unroll
        for (int d = 0; d < 4; d++) {
            uint32_t dst = ring_s + (uint32_t)(d * 512 + tid) * 48;
            const char* sp = gwb + (size_t)d * 256 * 48;
            cp16(dst, sp);
            cp16(dst + 16, sp + 16);
            cp16(dst + 32, sp + 32);
            cp_commit();
        }

        // Etab gathers (long-latency; also covers ring prologue)
        float giR[4], giZ[4], giN[4], dt4[4];
#pragma unroll
        for (int q = 0; q < 4; q++) {
            const float* e = g_Etab + (size_t)sh_it[r0 + q] * 768;
            giR[q] = e[j];
            giZ[q] = e[H + j];
            giN[q] = e[2 * H + j];
            dt4[q] = sh_dt[r0 + q];
        }

        // ---- GRU gate matmul: this half's 64 kp via ring ----
        ull aR[BT], aZ[BT], aN[BT];
#pragma unroll
        for (int r = 0; r < BT; r++) { aR[r] = 0ull; aZ[r] = 0ull; aN[r] = 0ull; }

#pragma unroll 1
        for (int i = 0; i < 28; i++) {
            asm volatile("cp.async.wait_group 3;" ::: "memory");
            const ull* slot = &ring[(size_t)((i & 3) * 512 + tid) * 6];
            ulonglong2 wa = *(const ulonglong2*)slot;
            ulonglong2 wb = *(const ulonglong2*)(slot + 2);
            ulonglong2 wc = *(const ulonglong2*)(slot + 4);
            {
                uint32_t dst = ring_s + (uint32_t)((i & 3) * 512 + tid) * 48;
                const char* sp = gwb + (size_t)(i + 4) * 256 * 48;
                cp16(dst, sp);
                cp16(dst + 16, sp + 16);
                cp16(dst + 32, sp + 32);
                cp_commit();
            }
            const int fi = half * 128 + 4 * i;
#pragma unroll
            for (int r = 0; r < BT; r++) {
                ulonglong2 hv = *(const ulonglong2*)&sh_h[r][fi];
                ffma2(aR[r], hv.x, wa.x);
                ffma2(aZ[r], hv.x, wa.y);
                ffma2(aN[r], hv.x, wb.x);
                ffma2(aR[r], hv.y, wb.y);
                ffma2(aZ[r], hv.y, wc.x);
                ffma2(aN[r], hv.y, wc.y);
            }
        }
        asm volatile("cp.async.wait_group 0;" ::: "memory");
#pragma unroll 1
        for (int i = 28; i < 32; i++) {
            const ull* slot = &ring[(size_t)((i & 3) * 512 + tid) * 6];
            ulonglong2 wa = *(const ulonglong2*)slot;
            ulonglong2 wb = *(const ulonglong2*)(slot + 2);
            ulonglong2 wc = *(const ulonglong2*)(slot + 4);
            const int fi = half * 128 + 4 * i;
#pragma unroll
            for (int r = 0; r < BT; r++) {
                ulonglong2 hv = *(const ulonglong2*)&sh_h[r][fi];
                ffma2(aR[r], hv.x, wa.x);
                ffma2(aZ[r], hv.x, wa.y);
                ffma2(aN[r], hv.x, wb.x);
                ffma2(aR[r], hv.y, wb.y);
                ffma2(aZ[r], hv.y, wc.x);
                ffma2(aN[r], hv.y, wc.y);
            }
        }

        // write partials for the OTHER half's rows (own stay in registers)
        {
            const int ro = (1 - half) * 4;
#pragma unroll
            for (int q = 0; q < 4; q++) {
                red[RG(half, 0, q)] = hsum2(aR[ro + q]);
                red[RG(half, 1, q)] = hsum2(aZ[ro + q]);
                red[RG(half, 2, q)] = hsum2(aN[ro + q]);
            }
        }
        __syncthreads();

        // combine + GRU elementwise (gate order r,z,n)
#pragma unroll
        for (int q = 0; q < 4; q++) {
            int r = r0 + q;
            float pR = hsum2(aR[r]) + red[RG(1 - half, 0, q)];
            float pZ = hsum2(aZ[r]) + red[RG(1 - half, 1, q)];
            float pN = hsum2(aN[r]) + red[RG(1 - half, 2, q)];
            float rg = sigm(giR[q] + pR + bhhr);
            float zg = sigm(giZ[q] + pZ + bhhz);
            float ng = ftanh(giN[q] + rg * (pN + bhhn));
            float hold = sh_h[r][j];
            hnew[q] = (1.f - zg) * ng + zg * hold;
        }
        __syncthreads();
#pragma unroll
        for (int q = 0; q < 4; q++) sh_h[r0 + q][j] = hnew[q];
        __syncthreads();

        // ---- RK4 ----
        float ksum[4], kv[4];
        ull acc[BT];
        float (*src)[H] = sh_h;

#pragma unroll 1
        for (int eval = 0; eval < 4; eval++) {
            // layer 1
            mm_partial(src, sW1, g_W1S, ring, ring_s, j, half, tid, acc);
            {
                const int ro = (1 - half) * 4;
#pragma unroll
                for (int q = 0; q < 4; q++) red[RG(half, 0, q)] = hsum2(acc[ro + q]);
            }
            __syncthreads();
#pragma unroll
            for (int q = 0; q < 4; q++) {
                int r = r0 + q;
                sh_a[r][j] = ftanh(hsum2(acc[r]) + red[RG(1 - half, 0, q)] + b1j);
            }
            __syncthreads();

            // layer 2
            mm_partial(sh_a, sW2, g_W2S, ring, ring_s, j, half, tid, acc);
            {
                const int ro = (1 - half) * 4;
#pragma unroll
                for (int q = 0; q < 4; q++) red[RG(half, 0, q)] = hsum2(acc[ro + q]);
            }
            __syncthreads();
#pragma unroll
            for (int q = 0; q < 4; q++) {
                kv[q] = hsum2(acc[r0 + q]) + red[RG(1 - half, 0, q)] + b2j;
            }

            if (eval == 0) {
#pragma unroll
                for (int q = 0; q < 4; q++) {
                    ksum[q] = kv[q];
                    sh_t[r0 + q][j] = hnew[q] + 0.5f * dt4[q] * kv[q];
                }
            } else if (eval == 1) {
#pragma unroll
                for (int q = 0; q < 4; q++) {
                    ksum[q] += 2.f * kv[q];
                    sh_t[r0 + q][j] = hnew[q] + 0.5f * dt4[q] * kv[q];
                }
            } else if (eval == 2) {
#pragma unroll
                for (int q = 0; q < 4; q++) {
                    ksum[q] += 2.f * kv[q];
                    sh_t[r0 + q][j] = hnew[q] + dt4[q] * kv[q];
                }
            } else {
#pragma unroll
                for (int q = 0; q < 4; q++) {
                    ksum[q] += kv[q];
                    hnew[q] = hnew[q] + (dt4[q] * (1.f / 6.f)) * ksum[q];
                    sh_h[r0 + q][j] = hnew[q];
                }
            }
            __syncthreads();
            src = sh_t;
        }
    }

#pragma unroll
    for (int q = 0; q < 4; q++) g_hfin[(b0 + r0 + q) * H + j] = hnew[q];
#undef RG
}

// ---------------- launch ----------------
extern "C" void kernel_launch(void* const* d_in, const int* in_sizes, int n_in,
                              void* d_out, int out_size)
{
    const int*   x      = (const int*)d_in[0];
    const float* t      = (const float*)d_in[1];
    const float* emb    = (const float*)d_in[2];
    const float* W_ih   = (const float*)d_in[3];
    const float* W_hh   = (const float*)d_in[4];
    const float* b_ih   = (const float*)d_in[5];
    const float* b_hh   = (const float*)d_in[6];
    const float* W1     = (const float*)d_in[7];
    const float* b1     = (const float*)d_in[8];
    const float* W2     = (const float*)d_in[9];
    const float* b2     = (const float*)d_in[10];
    const float* W_head = (const float*)d_in[11];
    const float* b_head = (const float*)d_in[12];
    float* out = (float*)d_out;

    float* etab_ptr = nullptr;
    float* hfin_ptr = nullptr;
    cudaGetSymbolAddress((void**)&etab_ptr, g_Etab);
    cudaGetSymbolAddress((void**)&hfin_ptr, g_hfin);

    const int smem_bytes = 2 * KCP * 256 * (int)sizeof(__half2)   // 64 KB cached W1/W2
                         + 12288 * (int)sizeof(ull)               // 96 KB ring
                         + 3 * BT * H * (int)sizeof(float)        // h/a/t 24 KB
                         + 2 * 3 * 4 * H * (int)sizeof(float)     // red 24 KB
                         + BT * (int)(sizeof(int) + sizeof(float));
    cudaFuncSetAttribute(rec_kernel, cudaFuncAttributeMaxDynamicSharedMemorySize, smem_bytes);

    prep_pack<<<(2 * GRU_IT * 256 * 6 + 255) / 256, 256>>>(W_hh, W1, W2);

    // Etab = item_emb @ W_ih^T + b_ih   [50000, 768]
    dim3 ge(768 / GN, (NITEMS + GM - 1) / GM);
    gemm_nt<<<ge, 256>>>(emb, W_ih, b_ih, etab_ptr, NITEMS, 768);

    rec_kernel<<<BSZ / BT, 512, smem_bytes>>>(x, t, b_hh, b1, b2);

    // out = h_fin @ W_head^T + b_head   [1024, 50000]
    dim3 gh((NITEMS + GN - 1) / GN, BSZ / GM);
    gemm_nt<<<gh, 256>>>(hfin_ptr, W_head, b_head, out, BSZ, NITEMS);
}